// round 1
// baseline (speedup 1.0000x reference)
#include <cuda_runtime.h>
#include <math.h>

#define NN 50000
#define EE 800000

// ---------------- device scratch (no allocations allowed) ----------------
__device__ int   g_is64;
__device__ int   g_cnt[NN];
__device__ int   g_off[NN];
__device__ int   g_cur[NN];
__device__ int   g_csr[EE];
__device__ float g_B1[128 * 256];
__device__ float g_B2[128 * 256];
__device__ float g_C[NN * 256];     // fused GEMM output [N, 256]: cols 0:128 = h@W_l (to aggregate), 128:256 = h@W_r
__device__ float g_h1[NN * 128];
__device__ float g_a[NN];
__device__ float g_c[NN];

__device__ __forceinline__ int edge_at(const void* ei, long i) {
    return g_is64 ? (int)((const long long*)ei)[i] : ((const int*)ei)[i];
}

// ---------------- int32 vs int64 edge_index detection ----------------
__global__ void k_detect(const void* ei) {
    const int* w = (const int*)ei;
    int all0 = 1;
#pragma unroll
    for (int i = 0; i < 64; i++) all0 &= (w[2 * i + 1] == 0);
    g_is64 = all0;  // node ids < 2^31, so int64 high words are all 0
}

// ---------------- CSR build ----------------
__global__ void k_zero_cnt() {
    int i = blockIdx.x * blockDim.x + threadIdx.x;
    if (i < NN) g_cnt[i] = 0;
}

__global__ void k_count(const void* ei) {
    int e = blockIdx.x * blockDim.x + threadIdx.x;
    if (e >= EE) return;
    int t = edge_at(ei, (long)EE + e);
    atomicAdd(&g_cnt[t], 1);
}

__global__ void k_scan() {
    __shared__ int sh[1024];
    int t = threadIdx.x;
    const int CH = (NN + 1023) / 1024;  // 49
    int base = t * CH;
    int sum = 0;
    for (int i = 0; i < CH; i++) {
        int idx = base + i;
        if (idx < NN) sum += g_cnt[idx];
    }
    sh[t] = sum;
    __syncthreads();
    for (int d = 1; d < 1024; d <<= 1) {
        int x = (t >= d) ? sh[t - d] : 0;
        __syncthreads();
        sh[t] += x;
        __syncthreads();
    }
    int run = sh[t] - sum;  // exclusive prefix
    for (int i = 0; i < CH; i++) {
        int idx = base + i;
        if (idx < NN) {
            g_off[idx] = run;
            g_cur[idx] = run;
            run += g_cnt[idx];
        }
    }
}

__global__ void k_scatter(const void* ei) {
    int e = blockIdx.x * blockDim.x + threadIdx.x;
    if (e >= EE) return;
    int s = edge_at(ei, e);
    int t = edge_at(ei, (long)EE + e);
    int pos = atomicAdd(&g_cur[t], 1);
    g_csr[pos] = s;
}

// ---------------- weight packing: B = [W_l | W_r] (128 x 256) ----------------
__global__ void k_pack(const float* __restrict__ Wl1, const float* __restrict__ Wr1,
                       const float* __restrict__ Wl2, const float* __restrict__ Wr2) {
    int i = blockIdx.x * blockDim.x + threadIdx.x;
    if (i >= 128 * 128) return;
    int k = i >> 7, n = i & 127;
    g_B1[k * 256 + n]       = Wl1[i];
    g_B1[k * 256 + 128 + n] = Wr1[i];
    g_B2[k * 256 + n]       = Wl2[i];
    g_B2[k * 256 + 128 + n] = Wr2[i];
}

// ---------------- fp32 SGEMM: C[M,256] = A[M,128] @ B[128,256] ----------------
// BM=128, BN=128, BK=16, 256 threads, 8x8 per thread. grid = (ceil(M/128), 2)
__global__ __launch_bounds__(256) void k_gemm(const float* __restrict__ xin, int layer, int M) {
    const float* __restrict__ A = layer ? g_h1 : xin;
    const float* __restrict__ B = layer ? g_B2 : g_B1;
    float* __restrict__ C = g_C;

    __shared__ float As[16][128];  // As[k][row]
    __shared__ float Bs[16][128];  // Bs[k][col]

    const int tid = threadIdx.x;
    const int tr = tid >> 4;   // 0..15
    const int tc = tid & 15;   // 0..15
    const int rowBase = blockIdx.x * 128;
    const int colBase = blockIdx.y * 128;

    float acc[8][8];
#pragma unroll
    for (int i = 0; i < 8; i++)
#pragma unroll
        for (int j = 0; j < 8; j++) acc[i][j] = 0.f;

    for (int k0 = 0; k0 < 128; k0 += 16) {
        // A tile: 128 rows x 16 cols, transposed into As[k][row]
#pragma unroll
        for (int l = 0; l < 2; l++) {
            int q = tid + l * 256;        // 0..511 float4 id
            int r = q >> 2;               // 0..127 row
            int c4 = q & 3;               // float4 within 16 k-cols
            int grow = rowBase + r;
            float4 v = make_float4(0.f, 0.f, 0.f, 0.f);
            if (grow < M) v = *(const float4*)&A[grow * 128 + k0 + c4 * 4];
            As[c4 * 4 + 0][r] = v.x;
            As[c4 * 4 + 1][r] = v.y;
            As[c4 * 4 + 2][r] = v.z;
            As[c4 * 4 + 3][r] = v.w;
        }
        // B tile: 16 rows x 128 cols, direct
#pragma unroll
        for (int l = 0; l < 2; l++) {
            int q = tid + l * 256;
            int kr = q >> 5;              // 0..15
            int c4 = q & 31;              // float4 within 128 cols
            *(float4*)&Bs[kr][c4 * 4] = *(const float4*)&B[(k0 + kr) * 256 + colBase + c4 * 4];
        }
        __syncthreads();
#pragma unroll
        for (int k = 0; k < 16; k++) {
            float a[8], b[8];
            *(float4*)&a[0] = *(const float4*)&As[k][tr * 8];
            *(float4*)&a[4] = *(const float4*)&As[k][tr * 8 + 4];
            *(float4*)&b[0] = *(const float4*)&Bs[k][tc * 8];
            *(float4*)&b[4] = *(const float4*)&Bs[k][tc * 8 + 4];
#pragma unroll
            for (int i = 0; i < 8; i++)
#pragma unroll
                for (int j = 0; j < 8; j++) acc[i][j] += a[i] * b[j];
        }
        __syncthreads();
    }
#pragma unroll
    for (int i = 0; i < 8; i++) {
        int grow = rowBase + tr * 8 + i;
        if (grow < M) {
            *(float4*)&C[grow * 256 + colBase + tc * 8] =
                make_float4(acc[i][0], acc[i][1], acc[i][2], acc[i][3]);
            *(float4*)&C[grow * 256 + colBase + tc * 8 + 4] =
                make_float4(acc[i][4], acc[i][5], acc[i][6], acc[i][7]);
        }
    }
}

// ---------------- layer 1 epilogue: CSR mean-aggregate + bias + relu ----------------
// one warp per target node; lane owns 4 feature cols (float4)
__global__ void k_epi1(const float* __restrict__ bl) {
    int gw = (blockIdx.x * blockDim.x + threadIdx.x) >> 5;
    int lane = threadIdx.x & 31;
    if (gw >= NN) return;
    int s = g_off[gw], cnt = g_cnt[gw];
    float4 a0 = make_float4(0.f, 0.f, 0.f, 0.f);
    float4 a1 = make_float4(0.f, 0.f, 0.f, 0.f);
    int e = 0;
    for (; e + 2 <= cnt; e += 2) {
        int j0 = g_csr[s + e];
        int j1 = g_csr[s + e + 1];
        float4 v0 = *(const float4*)&g_C[j0 * 256 + lane * 4];
        float4 v1 = *(const float4*)&g_C[j1 * 256 + lane * 4];
        a0.x += v0.x; a0.y += v0.y; a0.z += v0.z; a0.w += v0.w;
        a1.x += v1.x; a1.y += v1.y; a1.z += v1.z; a1.w += v1.w;
    }
    if (e < cnt) {
        int j = g_csr[s + e];
        float4 v = *(const float4*)&g_C[j * 256 + lane * 4];
        a0.x += v.x; a0.y += v.y; a0.z += v.z; a0.w += v.w;
    }
    float inv = 1.0f / (float)max(cnt, 1);
    float4 r = *(const float4*)&g_C[gw * 256 + 128 + lane * 4];
    float4 bb = *(const float4*)&bl[lane * 4];
    float4 o;
    o.x = fmaxf((a0.x + a1.x) * inv + r.x + bb.x, 0.f);
    o.y = fmaxf((a0.y + a1.y) * inv + r.y + bb.y, 0.f);
    o.z = fmaxf((a0.z + a1.z) * inv + r.z + bb.z, 0.f);
    o.w = fmaxf((a0.w + a1.w) * inv + r.w + bb.w, 0.f);
    *(float4*)&g_h1[gw * 128 + lane * 4] = o;
}

// ---------------- layer 2 epilogue: aggregate + bias, fused with W_e dots ----------------
// h2 never written to memory: a[i] = h2 . We[0:128], c[i] = h2 . We[128:256]
__global__ void k_epi2(const float* __restrict__ bl, const float* __restrict__ We) {
    int gw = (blockIdx.x * blockDim.x + threadIdx.x) >> 5;
    int lane = threadIdx.x & 31;
    if (gw >= NN) return;
    int s = g_off[gw], cnt = g_cnt[gw];
    float4 a0 = make_float4(0.f, 0.f, 0.f, 0.f);
    float4 a1 = make_float4(0.f, 0.f, 0.f, 0.f);
    int e = 0;
    for (; e + 2 <= cnt; e += 2) {
        int j0 = g_csr[s + e];
        int j1 = g_csr[s + e + 1];
        float4 v0 = *(const float4*)&g_C[j0 * 256 + lane * 4];
        float4 v1 = *(const float4*)&g_C[j1 * 256 + lane * 4];
        a0.x += v0.x; a0.y += v0.y; a0.z += v0.z; a0.w += v0.w;
        a1.x += v1.x; a1.y += v1.y; a1.z += v1.z; a1.w += v1.w;
    }
    if (e < cnt) {
        int j = g_csr[s + e];
        float4 v = *(const float4*)&g_C[j * 256 + lane * 4];
        a0.x += v.x; a0.y += v.y; a0.z += v.z; a0.w += v.w;
    }
    float inv = 1.0f / (float)max(cnt, 1);
    float4 r = *(const float4*)&g_C[gw * 256 + 128 + lane * 4];
    float4 bb = *(const float4*)&bl[lane * 4];
    float4 h;
    h.x = (a0.x + a1.x) * inv + r.x + bb.x;
    h.y = (a0.y + a1.y) * inv + r.y + bb.y;
    h.z = (a0.z + a1.z) * inv + r.z + bb.z;
    h.w = (a0.w + a1.w) * inv + r.w + bb.w;
    float4 w0 = *(const float4*)&We[lane * 4];
    float4 w1 = *(const float4*)&We[128 + lane * 4];
    float pa = h.x * w0.x + h.y * w0.y + h.z * w0.z + h.w * w0.w;
    float pc = h.x * w1.x + h.y * w1.y + h.z * w1.z + h.w * w1.w;
#pragma unroll
    for (int d = 16; d > 0; d >>= 1) {
        pa += __shfl_xor_sync(0xffffffffu, pa, d);
        pc += __shfl_xor_sync(0xffffffffu, pc, d);
    }
    if (lane == 0) {
        g_a[gw] = pa;
        g_c[gw] = pc;
    }
}

// ---------------- edge scoring: 8 bytes of gather per edge ----------------
__global__ void k_edge(const void* ei, const float* __restrict__ be, float* __restrict__ out) {
    int e = blockIdx.x * blockDim.x + threadIdx.x;
    if (e >= EE) return;
    int s = edge_at(ei, e);
    int t = edge_at(ei, (long)EE + e);
    float z = g_a[s] + g_c[t] + be[0];
    out[e] = 1.f / (1.f + expf(-z));
}

// ---------------- launcher ----------------
extern "C" void kernel_launch(void* const* d_in, const int* in_sizes, int n_in,
                              void* d_out, int out_size) {
    const float* x   = (const float*)d_in[0];
    const void*  ei  = d_in[1];
    const float* Wl1 = (const float*)d_in[2];
    const float* bl1 = (const float*)d_in[3];
    const float* Wr1 = (const float*)d_in[4];
    const float* Wl2 = (const float*)d_in[5];
    const float* bl2 = (const float*)d_in[6];
    const float* Wr2 = (const float*)d_in[7];
    const float* We  = (const float*)d_in[8];
    const float* be  = (const float*)d_in[9];
    float* out = (float*)d_out;

    k_detect<<<1, 1>>>(ei);
    k_zero_cnt<<<(NN + 255) / 256, 256>>>();
    k_count<<<(EE + 255) / 256, 256>>>(ei);
    k_scan<<<1, 1024>>>();
    k_scatter<<<(EE + 255) / 256, 256>>>(ei);
    k_pack<<<(128 * 128 + 255) / 256, 256>>>(Wl1, Wr1, Wl2, Wr2);

    dim3 gg((NN + 127) / 128, 2);
    const int epiBlocks = (NN * 32 + 255) / 256;

    k_gemm<<<gg, 256>>>(x, 0, NN);
    k_epi1<<<epiBlocks, 256>>>(bl1);
    k_gemm<<<gg, 256>>>(x, 1, NN);
    k_epi2<<<epiBlocks, 256>>>(bl2, We);
    k_edge<<<(EE + 255) / 256, 256>>>(ei, be, out);
}

// round 3
// speedup vs baseline: 2.0652x; 2.0652x over previous
#include <cuda_runtime.h>
#include <cuda_bf16.h>
#include <math.h>
#include <stdint.h>

#define NN 50000
#define EE 800000
#define NB 49  // ceil(NN/1024)

// ---------------- device scratch (no allocations allowed) ----------------
__device__ int   g_is64;
__device__ int   g_cnt[NN];
__device__ int   g_off[NN];
__device__ int   g_cur[NN];
__device__ int   g_csr[EE];
__device__ int   g_bsum[NB];
__device__ int   g_bbase[NB];
__device__ __align__(16) __nv_bfloat16 g_B1b[256 * 128];  // B_ex[n][k] = W[k][n], [Wl|Wr]
__device__ __align__(16) __nv_bfloat16 g_B2b[256 * 128];
__device__ __align__(16) __nv_bfloat16 g_h1b[NN * 128];
__device__ float g_C[NN * 256];   // cols 0:128 = h@W_l (to aggregate), 128:256 = h@W_r
__device__ float g_a[NN];
__device__ float g_c[NN];

__device__ __forceinline__ int edge_at(const void* ei, long i) {
    return g_is64 ? (int)((const long long*)ei)[i] : ((const int*)ei)[i];
}

__device__ __forceinline__ uint32_t smem_u32(const void* p) {
    uint32_t a;
    asm("{ .reg .u64 t; cvta.to.shared.u64 t, %1; cvt.u32.u64 %0, t; }" : "=r"(a) : "l"(p));
    return a;
}

// ---------------- int32 vs int64 edge_index detection ----------------
__global__ void k_detect(const void* ei) {
    const int* w = (const int*)ei;
    int all0 = 1;
#pragma unroll
    for (int i = 0; i < 64; i++) all0 &= (w[2 * i + 1] == 0);
    g_is64 = all0;
}

// ---------------- CSR build ----------------
__global__ void k_zero_cnt() {
    int i = blockIdx.x * blockDim.x + threadIdx.x;
    if (i < NN) g_cnt[i] = 0;
}

__global__ void k_count(const void* ei) {
    int e = blockIdx.x * blockDim.x + threadIdx.x;
    if (e >= EE) return;
    int t = edge_at(ei, (long)EE + e);
    atomicAdd(&g_cnt[t], 1);
}

// hierarchical exclusive scan of g_cnt -> g_off (coalesced)
__global__ void k_scan1() {
    __shared__ int ws[32];
    int tid = threadIdx.x, lane = tid & 31, w = tid >> 5;
    int i = blockIdx.x * 1024 + tid;
    int v = (i < NN) ? g_cnt[i] : 0;
    int x = v;
#pragma unroll
    for (int d = 1; d < 32; d <<= 1) { int t = __shfl_up_sync(~0u, x, d); if (lane >= d) x += t; }
    if (lane == 31) ws[w] = x;
    __syncthreads();
    if (w == 0) {
        int y = ws[lane];
#pragma unroll
        for (int d = 1; d < 32; d <<= 1) { int t = __shfl_up_sync(~0u, y, d); if (lane >= d) y += t; }
        ws[lane] = y;
    }
    __syncthreads();
    int base = w ? ws[w - 1] : 0;
    int incl = base + x;
    if (i < NN) g_off[i] = incl - v;
    if (tid == 1023) g_bsum[blockIdx.x] = incl;
}

__global__ void k_scan2() {  // 64 threads, scan NB=49 block sums
    __shared__ int s0;
    int tid = threadIdx.x, lane = tid & 31, w = tid >> 5;
    int v = (tid < NB) ? g_bsum[tid] : 0;
    int x = v;
#pragma unroll
    for (int d = 1; d < 32; d <<= 1) { int t = __shfl_up_sync(~0u, x, d); if (lane >= d) x += t; }
    if (w == 0 && lane == 31) s0 = x;
    __syncthreads();
    int excl = x - v + (w ? s0 : 0);
    if (tid < NB) g_bbase[tid] = excl;
}

__global__ void k_scan3() {
    int i = blockIdx.x * 1024 + threadIdx.x;
    if (i < NN) {
        int o = g_off[i] + g_bbase[blockIdx.x];
        g_off[i] = o;
        g_cur[i] = o;
    }
}

__global__ void k_scatter(const void* ei) {
    int e = blockIdx.x * blockDim.x + threadIdx.x;
    if (e >= EE) return;
    int s = edge_at(ei, e);
    int t = edge_at(ei, (long)EE + e);
    int pos = atomicAdd(&g_cur[t], 1);
    g_csr[pos] = s;
}

// ---------------- weight packing: B_ex[n][k] = W[k][n], bf16, [Wl|Wr] ----------------
__global__ void k_packb(const float* __restrict__ Wl1, const float* __restrict__ Wr1,
                        const float* __restrict__ Wl2, const float* __restrict__ Wr2) {
    int i = blockIdx.x * blockDim.x + threadIdx.x;
    if (i >= 256 * 128) return;
    int n = i >> 7, k = i & 127;
    float v1 = (n < 128) ? Wl1[k * 128 + n] : Wr1[k * 128 + (n - 128)];
    float v2 = (n < 128) ? Wl2[k * 128 + n] : Wr2[k * 128 + (n - 128)];
    g_B1b[i] = __float2bfloat16(v1);
    g_B2b[i] = __float2bfloat16(v2);
}

// ---------------- HMMA bf16 GEMM: C tile[128,128] = A[128,128] @ B_ex[colrange]^T ----------------
// mma.sync.aligned.m16n8k16 (plain sm_103 ISA; tcgen05 is 'a'-gated and unavailable here).
// 256 threads = 8 warps in 2(M) x 4(N); warp tile 64x32. Full K=128 staged in smem.
#define ASTRIDE 136  // 128 + 8 bf16 pad (272B rows; ldmatrix phase conflict-free)

__global__ __launch_bounds__(256) void k_gemm_mma(const float* __restrict__ x, int layer, int M) {
    extern __shared__ __nv_bfloat16 sm[];
    __nv_bfloat16* As = sm;                    // [128][ASTRIDE]
    __nv_bfloat16* Bs = sm + 128 * ASTRIDE;    // [128][ASTRIDE]

    const int tid = threadIdx.x;
    const int lane = tid & 31, w = tid >> 5;
    const int rowBase = blockIdx.x * 128;
    const int colBase = blockIdx.y * 128;

    // ---- load B tile: 128 n-rows x 128 k ----
    {
        const __nv_bfloat16* Bsrc = (layer ? g_B2b : g_B1b) + (size_t)colBase * 128;
        int r = tid >> 1, half = tid & 1;
        const uint4* src = (const uint4*)(Bsrc + r * 128 + half * 64);
        uint4* dst = (uint4*)(Bs + r * ASTRIDE + half * 64);
#pragma unroll
        for (int i = 0; i < 8; i++) dst[i] = src[i];
    }
    // ---- load A tile: 128 rows x 128 k (layer0: fp32 -> bf16 convert) ----
    {
        int r = tid >> 1, half = tid & 1;
        int grow = rowBase + r;
        if (layer == 0) {
            const float4* src = (const float4*)(x + (size_t)grow * 128 + half * 64);
            uint32_t* dst = (uint32_t*)(As + r * ASTRIDE + half * 64);
#pragma unroll
            for (int i = 0; i < 16; i++) {
                float4 v = make_float4(0.f, 0.f, 0.f, 0.f);
                if (grow < M) v = src[i];
                __nv_bfloat162 lo = __floats2bfloat162_rn(v.x, v.y);
                __nv_bfloat162 hi = __floats2bfloat162_rn(v.z, v.w);
                dst[i * 2]     = *(uint32_t*)&lo;
                dst[i * 2 + 1] = *(uint32_t*)&hi;
            }
        } else {
            const uint4* src = (const uint4*)(g_h1b + (size_t)grow * 128 + half * 64);
            uint4* dst = (uint4*)(As + r * ASTRIDE + half * 64);
            uint4 z = make_uint4(0u, 0u, 0u, 0u);
#pragma unroll
            for (int i = 0; i < 8; i++) dst[i] = (grow < M) ? src[i] : z;
        }
    }
    __syncthreads();

    const int wm = w >> 2;   // 0..1  (64-row slab)
    const int wn = w & 3;    // 0..3  (32-col slab)

    float acc[4][4][4];
#pragma unroll
    for (int i = 0; i < 4; i++)
#pragma unroll
        for (int j = 0; j < 4; j++)
#pragma unroll
            for (int q = 0; q < 4; q++) acc[i][j][q] = 0.f;

#pragma unroll
    for (int ks = 0; ks < 8; ks++) {
        const int k0 = ks * 16;
        uint32_t a[4][4];
#pragma unroll
        for (int mf = 0; mf < 4; mf++) {
            uint32_t addr = smem_u32(As + (wm * 64 + mf * 16 + (lane & 15)) * ASTRIDE + k0 + (lane >> 4) * 8);
            asm volatile("ldmatrix.sync.aligned.m8n8.x4.shared.b16 {%0,%1,%2,%3}, [%4];"
                         : "=r"(a[mf][0]), "=r"(a[mf][1]), "=r"(a[mf][2]), "=r"(a[mf][3]) : "r"(addr));
        }
        uint32_t b[4][2];
#pragma unroll
        for (int nh = 0; nh < 2; nh++) {
            uint32_t r0, r1, r2, r3;
            uint32_t addr = smem_u32(Bs + (wn * 32 + nh * 16 + (lane & 15)) * ASTRIDE + k0 + (lane >> 4) * 8);
            asm volatile("ldmatrix.sync.aligned.m8n8.x4.shared.b16 {%0,%1,%2,%3}, [%4];"
                         : "=r"(r0), "=r"(r1), "=r"(r2), "=r"(r3) : "r"(addr));
            b[nh * 2 + 0][0] = r0; b[nh * 2 + 0][1] = r2;
            b[nh * 2 + 1][0] = r1; b[nh * 2 + 1][1] = r3;
        }
#pragma unroll
        for (int mf = 0; mf < 4; mf++)
#pragma unroll
            for (int nf = 0; nf < 4; nf++) {
                asm volatile(
                    "mma.sync.aligned.m16n8k16.row.col.f32.bf16.bf16.f32 "
                    "{%0,%1,%2,%3}, {%4,%5,%6,%7}, {%8,%9}, {%0,%1,%2,%3};"
                    : "+f"(acc[mf][nf][0]), "+f"(acc[mf][nf][1]), "+f"(acc[mf][nf][2]), "+f"(acc[mf][nf][3])
                    : "r"(a[mf][0]), "r"(a[mf][1]), "r"(a[mf][2]), "r"(a[mf][3]),
                      "r"(b[nf][0]), "r"(b[nf][1]));
            }
    }

    // ---- epilogue: write fp32 C ----
#pragma unroll
    for (int mf = 0; mf < 4; mf++) {
        int r0 = rowBase + wm * 64 + mf * 16 + (lane >> 2);
#pragma unroll
        for (int nf = 0; nf < 4; nf++) {
            int col = colBase + wn * 32 + nf * 8 + (lane & 3) * 2;
            if (r0 < M) {
                float2* p = (float2*)(g_C + (size_t)r0 * 256 + col);
                *p = make_float2(acc[mf][nf][0], acc[mf][nf][1]);
            }
            if (r0 + 8 < M) {
                float2* p = (float2*)(g_C + (size_t)(r0 + 8) * 256 + col);
                *p = make_float2(acc[mf][nf][2], acc[mf][nf][3]);
            }
        }
    }
}

// ---------------- layer 1 epilogue: CSR mean-aggregate + bias + relu -> bf16 h1 ----------------
__global__ void k_epi1(const float* __restrict__ bl) {
    int gw = (blockIdx.x * blockDim.x + threadIdx.x) >> 5;
    int lane = threadIdx.x & 31;
    if (gw >= NN) return;
    int s = g_off[gw], cnt = g_cnt[gw];
    float4 a0 = make_float4(0.f, 0.f, 0.f, 0.f);
    float4 a1 = make_float4(0.f, 0.f, 0.f, 0.f);
    int e = 0;
    for (; e + 2 <= cnt; e += 2) {
        int j0 = g_csr[s + e];
        int j1 = g_csr[s + e + 1];
        float4 v0 = *(const float4*)&g_C[j0 * 256 + lane * 4];
        float4 v1 = *(const float4*)&g_C[j1 * 256 + lane * 4];
        a0.x += v0.x; a0.y += v0.y; a0.z += v0.z; a0.w += v0.w;
        a1.x += v1.x; a1.y += v1.y; a1.z += v1.z; a1.w += v1.w;
    }
    if (e < cnt) {
        int j = g_csr[s + e];
        float4 v = *(const float4*)&g_C[j * 256 + lane * 4];
        a0.x += v.x; a0.y += v.y; a0.z += v.z; a0.w += v.w;
    }
    float inv = 1.0f / (float)max(cnt, 1);
    float4 r = *(const float4*)&g_C[gw * 256 + 128 + lane * 4];
    float4 bb = *(const float4*)&bl[lane * 4];
    float ox = fmaxf((a0.x + a1.x) * inv + r.x + bb.x, 0.f);
    float oy = fmaxf((a0.y + a1.y) * inv + r.y + bb.y, 0.f);
    float oz = fmaxf((a0.z + a1.z) * inv + r.z + bb.z, 0.f);
    float ow = fmaxf((a0.w + a1.w) * inv + r.w + bb.w, 0.f);
    __nv_bfloat162 p0 = __floats2bfloat162_rn(ox, oy);
    __nv_bfloat162 p1 = __floats2bfloat162_rn(oz, ow);
    uint64_t pk = ((uint64_t)(*(uint32_t*)&p1) << 32) | (uint64_t)(*(uint32_t*)&p0);
    *(uint64_t*)(g_h1b + (size_t)gw * 128 + lane * 4) = pk;
}

// ---------------- layer 2 epilogue: aggregate + bias fused with W_e dots ----------------
__global__ void k_epi2(const float* __restrict__ bl, const float* __restrict__ We) {
    int gw = (blockIdx.x * blockDim.x + threadIdx.x) >> 5;
    int lane = threadIdx.x & 31;
    if (gw >= NN) return;
    int s = g_off[gw], cnt = g_cnt[gw];
    float4 a0 = make_float4(0.f, 0.f, 0.f, 0.f);
    float4 a1 = make_float4(0.f, 0.f, 0.f, 0.f);
    int e = 0;
    for (; e + 2 <= cnt; e += 2) {
        int j0 = g_csr[s + e];
        int j1 = g_csr[s + e + 1];
        float4 v0 = *(const float4*)&g_C[j0 * 256 + lane * 4];
        float4 v1 = *(const float4*)&g_C[j1 * 256 + lane * 4];
        a0.x += v0.x; a0.y += v0.y; a0.z += v0.z; a0.w += v0.w;
        a1.x += v1.x; a1.y += v1.y; a1.z += v1.z; a1.w += v1.w;
    }
    if (e < cnt) {
        int j = g_csr[s + e];
        float4 v = *(const float4*)&g_C[j * 256 + lane * 4];
        a0.x += v.x; a0.y += v.y; a0.z += v.z; a0.w += v.w;
    }
    float inv = 1.0f / (float)max(cnt, 1);
    float4 r = *(const float4*)&g_C[gw * 256 + 128 + lane * 4];
    float4 bb = *(const float4*)&bl[lane * 4];
    float hx = (a0.x + a1.x) * inv + r.x + bb.x;
    float hy = (a0.y + a1.y) * inv + r.y + bb.y;
    float hz = (a0.z + a1.z) * inv + r.z + bb.z;
    float hw = (a0.w + a1.w) * inv + r.w + bb.w;
    float4 w0 = *(const float4*)&We[lane * 4];
    float4 w1 = *(const float4*)&We[128 + lane * 4];
    float pa = hx * w0.x + hy * w0.y + hz * w0.z + hw * w0.w;
    float pc = hx * w1.x + hy * w1.y + hz * w1.z + hw * w1.w;
#pragma unroll
    for (int d = 16; d > 0; d >>= 1) {
        pa += __shfl_xor_sync(0xffffffffu, pa, d);
        pc += __shfl_xor_sync(0xffffffffu, pc, d);
    }
    if (lane == 0) {
        g_a[gw] = pa;
        g_c[gw] = pc;
    }
}

// ---------------- edge scoring ----------------
__global__ void k_edge(const void* ei, const float* __restrict__ be, float* __restrict__ out) {
    int e = blockIdx.x * blockDim.x + threadIdx.x;
    if (e >= EE) return;
    int s = edge_at(ei, e);
    int t = edge_at(ei, (long)EE + e);
    float z = g_a[s] + g_c[t] + be[0];
    out[e] = 1.f / (1.f + expf(-z));
}

// ---------------- launcher ----------------
extern "C" void kernel_launch(void* const* d_in, const int* in_sizes, int n_in,
                              void* d_out, int out_size) {
    const float* x   = (const float*)d_in[0];
    const void*  ei  = d_in[1];
    const float* Wl1 = (const float*)d_in[2];
    const float* bl1 = (const float*)d_in[3];
    const float* Wr1 = (const float*)d_in[4];
    const float* Wl2 = (const float*)d_in[5];
    const float* bl2 = (const float*)d_in[6];
    const float* Wr2 = (const float*)d_in[7];
    const float* We  = (const float*)d_in[8];
    const float* be  = (const float*)d_in[9];
    float* out = (float*)d_out;

    const int smemBytes = 2 * 128 * ASTRIDE * (int)sizeof(__nv_bfloat16);  // ~68 KB
    cudaFuncSetAttribute(k_gemm_mma, cudaFuncAttributeMaxDynamicSharedMemorySize, smemBytes);

    k_detect<<<1, 1>>>(ei);
    k_zero_cnt<<<(NN + 255) / 256, 256>>>();
    k_count<<<(EE + 255) / 256, 256>>>(ei);
    k_scan1<<<NB, 1024>>>();
    k_scan2<<<1, 64>>>();
    k_scan3<<<NB, 1024>>>();
    k_scatter<<<(EE + 255) / 256, 256>>>(ei);
    k_packb<<<(256 * 128 + 255) / 256, 256>>>(Wl1, Wr1, Wl2, Wr2);

    dim3 gg((NN + 127) / 128, 2);
    const int epiBlocks = (NN * 32 + 255) / 256;

    k_gemm_mma<<<gg, 256, smemBytes>>>(x, 0, NN);
    k_epi1<<<epiBlocks, 256>>>(bl1);
    k_gemm_mma<<<gg, 256, smemBytes>>>(x, 1, NN);
    k_epi2<<<epiBlocks, 256>>>(bl2, We);
    k_edge<<<(EE + 255) / 256, 256>>>(ei, be, out);
}